// round 2
// baseline (speedup 1.0000x reference)
#include <cuda_runtime.h>

// RankPooling via Woodbury identity:
//   w = 2C * X * (y - c),   (S + I/(2C)) c = S y,   S = X^T X  (T x T)
// Solved with Jacobi iteration: spectral radius ||S||/(1/2C) ~ 0.03.

#define BATCH 256
#define DDIM  768
#define TDIM  128
#define CHUNK 16
#define NCHUNK (DDIM / CHUNK)   // 48
#define A2C   2e-5f             // a = 2*C

// Scratch (allocation-free rule: __device__ globals)
__device__ float g_S[(size_t)BATCH * TDIM * TDIM];  // 16 MB
__device__ float g_g[BATCH * TDIM];                 // y - c per batch

// ---------------------------------------------------------------------------
// Kernel 1: per-batch Gram S = X^T X.  One CTA/batch, 256 threads,
// each thread owns an 8x8 tile of the 128x128 result. K (=D) streamed in
// 16-row chunks through shared with register double-buffering.
// ---------------------------------------------------------------------------
__global__ void __launch_bounds__(256) gram_kernel(const float* __restrict__ X) {
    const int b = blockIdx.x;
    const float4* __restrict__ g4 = (const float4*)(X + (size_t)b * DDIM * TDIM);

    __shared__ float sh[2][CHUNK * TDIM];   // 2 x 8 KB

    const int tid = threadIdx.x;
    const int tx  = tid & 15;   // column tile (j)
    const int ty  = tid >> 4;   // row tile (i)

    float acc[8][8];
#pragma unroll
    for (int i = 0; i < 8; ++i)
#pragma unroll
        for (int j = 0; j < 8; ++j) acc[i][j] = 0.f;

    // Prologue: load chunk 0 (512 float4 per chunk, 2 per thread)
    {
        float4* s4 = (float4*)sh[0];
        s4[tid]       = g4[tid];
        s4[tid + 256] = g4[tid + 256];
    }
    __syncthreads();

    for (int c = 0; c < NCHUNK; ++c) {
        const int cur = c & 1;

        float4 p0, p1;
        const bool more = (c + 1) < NCHUNK;
        if (more) {
            p0 = g4[(c + 1) * 512 + tid];
            p1 = g4[(c + 1) * 512 + tid + 256];
        }

        const float* shc = sh[cur];
#pragma unroll
        for (int k = 0; k < CHUNK; ++k) {
            const float4* row = (const float4*)(shc + k * TDIM);
            float4 a0 = row[tx * 2], a1 = row[tx * 2 + 1];
            float4 b0 = row[ty * 2], b1 = row[ty * 2 + 1];
            float av[8] = {a0.x, a0.y, a0.z, a0.w, a1.x, a1.y, a1.z, a1.w};
            float bv[8] = {b0.x, b0.y, b0.z, b0.w, b1.x, b1.y, b1.z, b1.w};
#pragma unroll
            for (int i = 0; i < 8; ++i)
#pragma unroll
                for (int j = 0; j < 8; ++j)
                    acc[i][j] = fmaf(bv[i], av[j], acc[i][j]);
        }
        __syncthreads();
        if (more) {
            float4* s4 = (float4*)sh[cur ^ 1];
            s4[tid]       = p0;
            s4[tid + 256] = p1;
        }
        __syncthreads();
    }

    float* Sb = g_S + (size_t)b * TDIM * TDIM;
#pragma unroll
    for (int i = 0; i < 8; ++i) {
        const int row = ty * 8 + i;
        float4* dst = (float4*)(Sb + row * TDIM + tx * 8);
        dst[0] = make_float4(acc[i][0], acc[i][1], acc[i][2], acc[i][3]);
        dst[1] = make_float4(acc[i][4], acc[i][5], acc[i][6], acc[i][7]);
    }
}

// ---------------------------------------------------------------------------
// Kernel 2: per-batch tiny solve.  One CTA/batch, 128 threads.
// Thread t keeps row t of S in registers.  b_t = (S y)_t with y_j = j+1.
// Jacobi: c <- a*(b - S c).  Contraction factor ~0.03 -> 13 iters ~ 1e-19.
// Emits g = y - c.
// ---------------------------------------------------------------------------
__global__ void __launch_bounds__(128) solve_kernel() {
    const int b = blockIdx.x;
    const int t = threadIdx.x;

    float r[TDIM];
    const float4* S4 = (const float4*)(g_S + (size_t)b * TDIM * TDIM + t * TDIM);
#pragma unroll
    for (int i = 0; i < TDIM / 4; ++i) {
        float4 v = S4[i];
        r[4 * i]     = v.x;
        r[4 * i + 1] = v.y;
        r[4 * i + 2] = v.z;
        r[4 * i + 3] = v.w;
    }

    float bt = 0.f;
#pragma unroll
    for (int j = 0; j < TDIM; ++j) bt = fmaf(r[j], (float)(j + 1), bt);

    __shared__ float csh[TDIM];
    float ct = bt * A2C;            // first iterate from c = 0
    csh[t] = ct;
    __syncthreads();

    for (int it = 0; it < 13; ++it) {
        float dot = 0.f;
#pragma unroll
        for (int j = 0; j < TDIM; ++j) dot = fmaf(r[j], csh[j], dot);
        float cnew = (bt - dot) * A2C;
        __syncthreads();
        csh[t] = cnew;
        __syncthreads();
    }

    g_g[b * TDIM + t] = (float)(t + 1) - csh[t];
}

// ---------------------------------------------------------------------------
// Kernel 3: w = a * X * g.  One CTA/batch, 8 warps; each warp handles a row d
// (dot of 128 contiguous floats), LDG.128 coalesced, shfl reduction.
// ---------------------------------------------------------------------------
__global__ void __launch_bounds__(256) out_kernel(const float* __restrict__ X,
                                                  float* __restrict__ W) {
    const int b = blockIdx.x;
    const float* Xb = X + (size_t)b * DDIM * TDIM;

    __shared__ float gsh[TDIM];
    if (threadIdx.x < TDIM) gsh[threadIdx.x] = g_g[b * TDIM + threadIdx.x];
    __syncthreads();

    const int warp = threadIdx.x >> 5;
    const int lane = threadIdx.x & 31;
    const float g0 = gsh[lane * 4];
    const float g1 = gsh[lane * 4 + 1];
    const float g2 = gsh[lane * 4 + 2];
    const float g3 = gsh[lane * 4 + 3];

    for (int d = warp; d < DDIM; d += 8) {
        float4 v = ((const float4*)(Xb + d * TDIM))[lane];
        float s = v.x * g0;
        s = fmaf(v.y, g1, s);
        s = fmaf(v.z, g2, s);
        s = fmaf(v.w, g3, s);
#pragma unroll
        for (int o = 16; o > 0; o >>= 1) s += __shfl_xor_sync(0xffffffffu, s, o);
        if (lane == 0) W[b * DDIM + d] = A2C * s;
    }
}

// ---------------------------------------------------------------------------
extern "C" void kernel_launch(void* const* d_in, const int* in_sizes, int n_in,
                              void* d_out, int out_size) {
    const float* X = (const float*)d_in[0];
    float* W = (float*)d_out;

    gram_kernel<<<BATCH, 256>>>(X);
    solve_kernel<<<BATCH, TDIM>>>();
    out_kernel<<<BATCH, 256>>>(X, W);
}

// round 5
// speedup vs baseline: 2.7504x; 2.7504x over previous
#include <cuda_runtime.h>
#include <cuda_bf16.h>
#include <cstdint>

// RankPooling via Woodbury:
//   w = 2C * X * (y - c),   (S + I/(2C)) c = S y,   S = X^T X  (128x128)
// Gram via bf16 mma.sync (HMMA) — tcgen05 unavailable at compute_100 target.
// Jacobi solve (contraction ||S||*2C ~ 0.03), then w = 2C * X * (y - c).

#define BATCH 256
#define DDIM  768
#define TDIM  128
#define CK    32               // d-rows per chunk
#define NCH   (DDIM / CK)      // 24
#define A2C   2e-5f

__device__ float g_S[(size_t)BATCH * TDIM * TDIM];  // 16 MB scratch
__device__ float g_g[BATCH * TDIM];

__device__ __forceinline__ uint32_t smem_u32(const void* p) {
    uint32_t a;
    asm("{ .reg .u64 t; cvta.to.shared.u64 t, %1; cvt.u32.u64 %0, t; }" : "=r"(a) : "l"(p));
    return a;
}

// ---------------------------------------------------------------------------
// Kernel 1: per-batch Gram S = X^T X via bf16 mma.sync m16n8k16.
// One CTA/batch, 256 threads (8 warps as 2(M) x 4(N); warp tile 64x32).
// SMEM: double-buffered bf16 tile [CK=32 d-rows][128 t], 256 B/row,
// XOR swizzle: 16B-chunk index ^= (row & 7)  -> conflict-free STS + LDSM.
// ---------------------------------------------------------------------------
__global__ void __launch_bounds__(256, 2) gram_kernel(const float* __restrict__ X) {
    __shared__ __align__(128) __nv_bfloat16 sh[2][CK * TDIM];  // 2 x 8 KB

    const int b    = blockIdx.x;
    const int tid  = threadIdx.x;
    const int lane = tid & 31;
    const int wid  = tid >> 5;
    const int warp_m = wid >> 2;   // 0..1 -> m0 = warp_m*64
    const int warp_n = wid & 3;    // 0..3 -> n0 = warp_n*32

    const float4* __restrict__ g4 = (const float4*)(X + (size_t)b * DDIM * TDIM);
    const uint32_t sb[2] = { smem_u32(sh[0]), smem_u32(sh[1]) };

    float acc[4][4][4];
#pragma unroll
    for (int i = 0; i < 4; ++i)
#pragma unroll
        for (int j = 0; j < 4; ++j)
#pragma unroll
            for (int k = 0; k < 4; ++k) acc[i][j][k] = 0.f;

    // --- chunk load/store helpers (4 float4 per thread per chunk) ---
    float4 va[4];
    auto ldchunk = [&](int c) {
        const float4* p = g4 + c * (CK * TDIM / 4);
#pragma unroll
        for (int i = 0; i < 4; ++i) va[i] = p[tid + 256 * i];
    };
    auto stchunk = [&](uint32_t base) {
#pragma unroll
        for (int i = 0; i < 4; ++i) {
            const int idx = tid + 256 * i;
            const int row = idx >> 5;        // d-row 0..31
            const int c4  = idx & 31;        // float4 column
            const uint32_t addr = base + row * 256
                                + ((((c4 >> 1) ^ (row & 7))) << 4) + ((c4 & 1) * 8);
            __nv_bfloat162 lo = __floats2bfloat162_rn(va[i].x, va[i].y);
            __nv_bfloat162 hi = __floats2bfloat162_rn(va[i].z, va[i].w);
            asm volatile("st.shared.v2.b32 [%0], {%1, %2};"
                         :: "r"(addr), "r"(*(uint32_t*)&lo), "r"(*(uint32_t*)&hi)
                         : "memory");
        }
    };

    // ldmatrix lane-address components (trans pattern):
    //   A (m16k16, from [k][m] memory): krow = k0+(L&7)+((L&16)?8:0), mcol = m0+((L&8)?8:0)
    //   B (k16n8x2, from [k][n] memory): krow = k0+(L&7)+((L&8)?8:0),  ncol = n0+((L&16)?8:0)
    const int a_kr = (lane & 7) + ((lane & 16) ? 8 : 0);
    const int a_mc = warp_m * 64 + ((lane & 8) ? 8 : 0);
    const int b_kr = (lane & 7) + ((lane & 8) ? 8 : 0);
    const int b_nc = warp_n * 32 + ((lane & 16) ? 8 : 0);

    ldchunk(0);
    stchunk(sb[0]);
    __syncthreads();

    for (int c = 0; c < NCH; ++c) {
        const int cur = c & 1;
        if (c + 1 < NCH) ldchunk(c + 1);

        const uint32_t base = sb[cur];
#pragma unroll
        for (int ks = 0; ks < CK / 16; ++ks) {
            const int k0 = ks * 16;
            uint32_t ar[4][4], br[2][4];
#pragma unroll
            for (int mi = 0; mi < 4; ++mi) {
                const int kr = k0 + a_kr;
                const int mc = a_mc + mi * 16;
                const uint32_t ad = base + kr * 256 + (((mc >> 3) ^ (kr & 7)) << 4);
                asm volatile(
                    "ldmatrix.sync.aligned.m8n8.x4.trans.shared.b16 {%0,%1,%2,%3}, [%4];"
                    : "=r"(ar[mi][0]), "=r"(ar[mi][1]), "=r"(ar[mi][2]), "=r"(ar[mi][3])
                    : "r"(ad));
            }
#pragma unroll
            for (int nj = 0; nj < 2; ++nj) {
                const int kr = k0 + b_kr;
                const int nc = b_nc + nj * 16;
                const uint32_t ad = base + kr * 256 + (((nc >> 3) ^ (kr & 7)) << 4);
                asm volatile(
                    "ldmatrix.sync.aligned.m8n8.x4.trans.shared.b16 {%0,%1,%2,%3}, [%4];"
                    : "=r"(br[nj][0]), "=r"(br[nj][1]), "=r"(br[nj][2]), "=r"(br[nj][3])
                    : "r"(ad));
            }
#pragma unroll
            for (int mi = 0; mi < 4; ++mi)
#pragma unroll
                for (int jj = 0; jj < 4; ++jj) {
                    const uint32_t b0 = br[jj >> 1][(jj & 1) * 2];
                    const uint32_t b1 = br[jj >> 1][(jj & 1) * 2 + 1];
                    asm volatile(
                        "mma.sync.aligned.m16n8k16.row.col.f32.bf16.bf16.f32 "
                        "{%0,%1,%2,%3}, {%4,%5,%6,%7}, {%8,%9}, {%0,%1,%2,%3};"
                        : "+f"(acc[mi][jj][0]), "+f"(acc[mi][jj][1]),
                          "+f"(acc[mi][jj][2]), "+f"(acc[mi][jj][3])
                        : "r"(ar[mi][0]), "r"(ar[mi][1]), "r"(ar[mi][2]), "r"(ar[mi][3]),
                          "r"(b0), "r"(b1));
                }
        }
        __syncthreads();
        if (c + 1 < NCH) stchunk(sb[cur ^ 1]);
        __syncthreads();
    }

    // Epilogue: write S tiles (float2 per mma accumulator pair)
    float* Sb = g_S + (size_t)b * TDIM * TDIM;
    const int r  = lane >> 2;
    const int cq = (lane & 3) * 2;
#pragma unroll
    for (int mi = 0; mi < 4; ++mi)
#pragma unroll
        for (int jj = 0; jj < 4; ++jj) {
            const int row0 = warp_m * 64 + mi * 16 + r;
            const int col  = warp_n * 32 + jj * 8 + cq;
            *(float2*)(Sb + (size_t)row0 * TDIM + col)
                = make_float2(acc[mi][jj][0], acc[mi][jj][1]);
            *(float2*)(Sb + (size_t)(row0 + 8) * TDIM + col)
                = make_float2(acc[mi][jj][2], acc[mi][jj][3]);
        }
}

// ---------------------------------------------------------------------------
// Kernel 2: per-batch tiny solve, Jacobi. Row t of S in registers.
// ---------------------------------------------------------------------------
__global__ void __launch_bounds__(128) solve_kernel() {
    const int b = blockIdx.x;
    const int t = threadIdx.x;

    float r[TDIM];
    const float4* S4 = (const float4*)(g_S + (size_t)b * TDIM * TDIM + t * TDIM);
#pragma unroll
    for (int i = 0; i < TDIM / 4; ++i) {
        float4 v = S4[i];
        r[4 * i] = v.x; r[4 * i + 1] = v.y; r[4 * i + 2] = v.z; r[4 * i + 3] = v.w;
    }

    float bt = 0.f;
#pragma unroll
    for (int j = 0; j < TDIM; ++j) bt = fmaf(r[j], (float)(j + 1), bt);

    __shared__ float csh[TDIM];
    csh[t] = bt * A2C;
    __syncthreads();

    for (int it = 0; it < 8; ++it) {
        float dot = 0.f;
#pragma unroll
        for (int j = 0; j < TDIM; ++j) dot = fmaf(r[j], csh[j], dot);
        float cnew = (bt - dot) * A2C;
        __syncthreads();
        csh[t] = cnew;
        __syncthreads();
    }

    g_g[b * TDIM + t] = (float)(t + 1) - csh[t];
}

// ---------------------------------------------------------------------------
// Kernel 3: w = 2C * X * g
// ---------------------------------------------------------------------------
__global__ void __launch_bounds__(256) out_kernel(const float* __restrict__ X,
                                                  float* __restrict__ W) {
    const int b = blockIdx.x;
    const float* Xb = X + (size_t)b * DDIM * TDIM;

    __shared__ float gsh[TDIM];
    if (threadIdx.x < TDIM) gsh[threadIdx.x] = g_g[b * TDIM + threadIdx.x];
    __syncthreads();

    const int warp = threadIdx.x >> 5;
    const int lane = threadIdx.x & 31;
    const float g0 = gsh[lane * 4];
    const float g1 = gsh[lane * 4 + 1];
    const float g2 = gsh[lane * 4 + 2];
    const float g3 = gsh[lane * 4 + 3];

    for (int d = warp; d < DDIM; d += 8) {
        float4 v = ((const float4*)(Xb + d * TDIM))[lane];
        float s = v.x * g0;
        s = fmaf(v.y, g1, s);
        s = fmaf(v.z, g2, s);
        s = fmaf(v.w, g3, s);
#pragma unroll
        for (int o = 16; o > 0; o >>= 1) s += __shfl_xor_sync(0xffffffffu, s, o);
        if (lane == 0) W[b * DDIM + d] = A2C * s;
    }
}

// ---------------------------------------------------------------------------
extern "C" void kernel_launch(void* const* d_in, const int* in_sizes, int n_in,
                              void* d_out, int out_size) {
    const float* X = (const float*)d_in[0];
    float* W = (float*)d_out;

    gram_kernel<<<BATCH, 256>>>(X);
    solve_kernel<<<BATCH, TDIM>>>();
    out_kernel<<<BATCH, 256>>>(X, W);
}

// round 6
// speedup vs baseline: 3.8313x; 1.3930x over previous
#include <cuda_runtime.h>
#include <cuda_bf16.h>
#include <cstdint>

// RankPooling via Woodbury, fully fused:
//   S = X^T X (bf16 HMMA, accumulators stay in registers)
//   (S + I/(2C)) c = S y  via Jacobi on the register-resident S
//   w = 2C * X * (y - c)  second streaming pass over X
// One CTA per batch; nothing round-trips through global scratch.

#define BATCH 256
#define DDIM  768
#define TDIM  128
#define CK    32               // d-rows per chunk
#define NCH   (DDIM / CK)      // 24
#define A2C   2e-5f

__device__ __forceinline__ uint32_t smem_u32(const void* p) {
    uint32_t a;
    asm("{ .reg .u64 t; cvta.to.shared.u64 t, %1; cvt.u32.u64 %0, t; }" : "=r"(a) : "l"(p));
    return a;
}

__global__ void __launch_bounds__(256, 2) fused_kernel(const float* __restrict__ X,
                                                       float* __restrict__ W) {
    __shared__ __align__(128) __nv_bfloat16 sh[2][CK * TDIM];  // 16 KB
    __shared__ float vsh[TDIM];                                 // c / y / g vector
    __shared__ float part[4][TDIM];                             // warp_n partials

    const int b    = blockIdx.x;
    const int tid  = threadIdx.x;
    const int lane = tid & 31;
    const int wid  = tid >> 5;
    const int warp_m = wid >> 2;   // 0..1 -> m0 = warp_m*64
    const int warp_n = wid & 3;    // 0..3 -> n0 = warp_n*32

    const float*  __restrict__ Xb = X + (size_t)b * DDIM * TDIM;
    const float4* __restrict__ g4 = (const float4*)Xb;
    const uint32_t sb[2] = { smem_u32(sh[0]), smem_u32(sh[1]) };

    float acc[4][4][4];
#pragma unroll
    for (int i = 0; i < 4; ++i)
#pragma unroll
        for (int j = 0; j < 4; ++j)
#pragma unroll
            for (int k = 0; k < 4; ++k) acc[i][j][k] = 0.f;

    // ================= Phase A: Gram mainloop (bf16 mma.sync) =================
    {
        float4 va[4];
        auto ldchunk = [&](int c) {
            const float4* p = g4 + c * (CK * TDIM / 4);
#pragma unroll
            for (int i = 0; i < 4; ++i) va[i] = p[tid + 256 * i];
        };
        auto stchunk = [&](uint32_t base) {
#pragma unroll
            for (int i = 0; i < 4; ++i) {
                const int idx = tid + 256 * i;
                const int row = idx >> 5;
                const int c4  = idx & 31;
                const uint32_t addr = base + row * 256
                                    + ((((c4 >> 1) ^ (row & 7))) << 4) + ((c4 & 1) * 8);
                __nv_bfloat162 lo = __floats2bfloat162_rn(va[i].x, va[i].y);
                __nv_bfloat162 hi = __floats2bfloat162_rn(va[i].z, va[i].w);
                asm volatile("st.shared.v2.b32 [%0], {%1, %2};"
                             :: "r"(addr), "r"(*(uint32_t*)&lo), "r"(*(uint32_t*)&hi)
                             : "memory");
            }
        };

        const int a_kr = (lane & 7) + ((lane & 16) ? 8 : 0);
        const int a_mc = warp_m * 64 + ((lane & 8) ? 8 : 0);
        const int b_kr = (lane & 7) + ((lane & 8) ? 8 : 0);
        const int b_nc = warp_n * 32 + ((lane & 16) ? 8 : 0);

        ldchunk(0);
        stchunk(sb[0]);
        __syncthreads();

        for (int c = 0; c < NCH; ++c) {
            const int cur = c & 1;
            if (c + 1 < NCH) ldchunk(c + 1);

            const uint32_t base = sb[cur];
#pragma unroll
            for (int ks = 0; ks < CK / 16; ++ks) {
                const int k0 = ks * 16;
                uint32_t ar[4][4], br[2][4];
#pragma unroll
                for (int mi = 0; mi < 4; ++mi) {
                    const int kr = k0 + a_kr;
                    const int mc = a_mc + mi * 16;
                    const uint32_t ad = base + kr * 256 + (((mc >> 3) ^ (kr & 7)) << 4);
                    asm volatile(
                        "ldmatrix.sync.aligned.m8n8.x4.trans.shared.b16 {%0,%1,%2,%3}, [%4];"
                        : "=r"(ar[mi][0]), "=r"(ar[mi][1]), "=r"(ar[mi][2]), "=r"(ar[mi][3])
                        : "r"(ad));
                }
#pragma unroll
                for (int nj = 0; nj < 2; ++nj) {
                    const int kr = k0 + b_kr;
                    const int nc = b_nc + nj * 16;
                    const uint32_t ad = base + kr * 256 + (((nc >> 3) ^ (kr & 7)) << 4);
                    asm volatile(
                        "ldmatrix.sync.aligned.m8n8.x4.trans.shared.b16 {%0,%1,%2,%3}, [%4];"
                        : "=r"(br[nj][0]), "=r"(br[nj][1]), "=r"(br[nj][2]), "=r"(br[nj][3])
                        : "r"(ad));
                }
#pragma unroll
                for (int mi = 0; mi < 4; ++mi)
#pragma unroll
                    for (int jj = 0; jj < 4; ++jj) {
                        const uint32_t b0 = br[jj >> 1][(jj & 1) * 2];
                        const uint32_t b1 = br[jj >> 1][(jj & 1) * 2 + 1];
                        asm volatile(
                            "mma.sync.aligned.m16n8k16.row.col.f32.bf16.bf16.f32 "
                            "{%0,%1,%2,%3}, {%4,%5,%6,%7}, {%8,%9}, {%0,%1,%2,%3};"
                            : "+f"(acc[mi][jj][0]), "+f"(acc[mi][jj][1]),
                              "+f"(acc[mi][jj][2]), "+f"(acc[mi][jj][3])
                            : "r"(ar[mi][0]), "r"(ar[mi][1]), "r"(ar[mi][2]), "r"(ar[mi][3]),
                              "r"(b0), "r"(b1));
                    }
            }
            __syncthreads();
            if (c + 1 < NCH) stchunk(sb[cur ^ 1]);
            __syncthreads();
        }
    }

    // ============ Phase B: Jacobi solve on register-resident S ============
    // Thread's acc[mi][jj][k] covers rows {R0, R0+8}, R0 = warp_m*64+mi*16+r,
    // cols {c0, c0+1}, c0 = warp_n*32+jj*8+(lane&3)*2.
    const int r  = lane >> 2;
    const int cq = (lane & 3) * 2;

    auto matvec_sv = [&]() -> float {
        float p[4][2];
#pragma unroll
        for (int mi = 0; mi < 4; ++mi) { p[mi][0] = 0.f; p[mi][1] = 0.f; }
#pragma unroll
        for (int jj = 0; jj < 4; ++jj) {
            const float v0 = vsh[warp_n * 32 + jj * 8 + cq];
            const float v1 = vsh[warp_n * 32 + jj * 8 + cq + 1];
#pragma unroll
            for (int mi = 0; mi < 4; ++mi) {
                p[mi][0] = fmaf(acc[mi][jj][0], v0, fmaf(acc[mi][jj][1], v1, p[mi][0]));
                p[mi][1] = fmaf(acc[mi][jj][2], v0, fmaf(acc[mi][jj][3], v1, p[mi][1]));
            }
        }
#pragma unroll
        for (int mi = 0; mi < 4; ++mi)
#pragma unroll
            for (int h = 0; h < 2; ++h) {
                float s = p[mi][h];
                s += __shfl_xor_sync(0xffffffffu, s, 1);
                s += __shfl_xor_sync(0xffffffffu, s, 2);
                p[mi][h] = s;
            }
        __syncthreads();                 // previous part[] reads complete
        if ((lane & 3) == 0) {
#pragma unroll
            for (int mi = 0; mi < 4; ++mi) {
                part[warp_n][warp_m * 64 + mi * 16 + r]     = p[mi][0];
                part[warp_n][warp_m * 64 + mi * 16 + 8 + r] = p[mi][1];
            }
        }
        __syncthreads();
        float sv = 0.f;
        if (tid < TDIM)
            sv = part[0][tid] + part[1][tid] + part[2][tid] + part[3][tid];
        return sv;
    };

    // b = S y,  y_t = t+1
    if (tid < TDIM) vsh[tid] = (float)(tid + 1);
    __syncthreads();
    const float bt = matvec_sv();

    // c0 = 2C * b; iterate c <- 2C*(b - S c).  Contraction ~0.03.
    if (tid < TDIM) vsh[tid] = bt * A2C;
    __syncthreads();
    for (int it = 0; it < 6; ++it) {
        const float sv = matvec_sv();
        if (tid < TDIM) vsh[tid] = (bt - sv) * A2C;
        __syncthreads();
    }
    // g = y - c
    if (tid < TDIM) vsh[tid] = (float)(tid + 1) - vsh[tid];
    __syncthreads();

    // ================= Phase C: w = 2C * X * g =================
    const float gv0 = vsh[lane * 4];
    const float gv1 = vsh[lane * 4 + 1];
    const float gv2 = vsh[lane * 4 + 2];
    const float gv3 = vsh[lane * 4 + 3];

    for (int d = wid; d < DDIM; d += 8) {
        float4 v = ((const float4*)(Xb + (size_t)d * TDIM))[lane];
        float s = v.x * gv0;
        s = fmaf(v.y, gv1, s);
        s = fmaf(v.z, gv2, s);
        s = fmaf(v.w, gv3, s);
#pragma unroll
        for (int o = 16; o > 0; o >>= 1) s += __shfl_xor_sync(0xffffffffu, s, o);
        if (lane == 0) W[b * DDIM + d] = A2C * s;
    }
}

// ---------------------------------------------------------------------------
extern "C" void kernel_launch(void* const* d_in, const int* in_sizes, int n_in,
                              void* d_out, int out_size) {
    const float* X = (const float*)d_in[0];
    float* W = (float*)d_out;
    fused_kernel<<<BATCH, 256>>>(X, W);
}